// round 4
// baseline (speedup 1.0000x reference)
#include <cuda_runtime.h>
#include <math.h>

// ============================================================================
// SimMIM forward: patchify -> masked embed -> 6-layer ViT -> pixel head -> L1
// Shapes: B=64, IMG=224, P=16, N=196, DIM=768, HEADS=12, dh=64, MLP=3072
// Round 0: fp32 SIMT baseline. GEMMs: 128x128x8 tiles, 8x8 per thread.
// ============================================================================

#define BATCH   64
#define NTOK    196
#define DIM     768
#define QKVDIM  2304
#define MLPDIM  3072
#define HEADS   12
#define DH      64
#define DEPTH   6
#define NMASK   98
#define TOKENS  (BATCH * NTOK)          // 12544
#define TOTELEM ((size_t)TOKENS * DIM)  // 9,633,792

// ---- scratch (static device memory; no allocations allowed) ----
__device__ float  g_patches[TOKENS * DIM];
__device__ float  g_x      [TOKENS * DIM];
__device__ float  g_h      [TOKENS * DIM];
__device__ float  g_qkv    [TOKENS * QKVDIM];
__device__ float  g_attn   [TOKENS * DIM];
__device__ float  g_hid    [(size_t)TOKENS * MLPDIM];
__device__ float  g_pred   [TOKENS * DIM];
__device__ int    g_mask   [BATCH * NTOK];
__device__ double g_part   [1024];

// ============================================================================
// patchify: img (B,224,224,3) -> patches (B,196,768)
// patch n = gi*14+gj ; feature d = pi*48 + pj*3 + c
// ============================================================================
__global__ void patchify_kernel(const float* __restrict__ img) {
    size_t i = (size_t)blockIdx.x * blockDim.x + threadIdx.x;
    if (i >= TOTELEM) return;
    int d  = (int)(i % DIM);
    int n  = (int)((i / DIM) % NTOK);
    int b  = (int)(i / ((size_t)DIM * NTOK));
    int gi = n / 14, gj = n % 14;
    int pi = d / 48; int rem = d % 48; int pj = rem / 3; int c = rem % 3;
    size_t src = (((size_t)b * 224 + gi * 16 + pi) * 224 + (gj * 16 + pj)) * 3 + c;
    g_patches[i] = img[src];
}

// ============================================================================
// top-k mask: per batch row, masked iff rank < NMASK (ties by lower index,
// matching jax.lax.top_k; set-equality is all the loss needs)
// ============================================================================
__global__ void topk_kernel(const float* __restrict__ noise) {
    int b = blockIdx.x;
    __shared__ float v[NTOK];
    int t = threadIdx.x;
    if (t < NTOK) v[t] = noise[b * NTOK + t];
    __syncthreads();
    if (t < NTOK) {
        float mv = v[t];
        int rank = 0;
        for (int j = 0; j < NTOK; j++)
            rank += (v[j] > mv) || (v[j] == mv && j < t);
        g_mask[b * NTOK + t] = (rank < NMASK) ? 1 : 0;
    }
}

// ============================================================================
// finalize tokens: x = masked ? mask_token+pe : x+pe   (pe = pos_emb[n+1])
// ============================================================================
__global__ void finalize_tokens(const float* __restrict__ pos_emb,
                                const float* __restrict__ mask_token) {
    size_t i = (size_t)blockIdx.x * blockDim.x + threadIdx.x;
    if (i >= TOTELEM) return;
    int d  = (int)(i % DIM);
    int n  = (int)((i / DIM) % NTOK);
    int bn = (int)(i / DIM);
    float pe = pos_emb[(size_t)(n + 1) * DIM + d];
    g_x[i] = g_mask[bn] ? (mask_token[d] + pe) : (g_x[i] + pe);
}

// ============================================================================
// LayerNorm: one block per token row (768), 256 threads, 3 elems/thread
// ============================================================================
__global__ void ln_kernel(const float* __restrict__ x,
                          const float* __restrict__ s,
                          const float* __restrict__ bp,
                          float* __restrict__ out) {
    int row = blockIdx.x;
    int t = threadIdx.x;
    const float* xr = x + (size_t)row * DIM;
    float v0 = xr[t], v1 = xr[t + 256], v2 = xr[t + 512];
    __shared__ float red[256];
    red[t] = v0 + v1 + v2;
    __syncthreads();
    for (int o = 128; o; o >>= 1) { if (t < o) red[t] += red[t + o]; __syncthreads(); }
    float mean = red[0] * (1.0f / DIM);
    __syncthreads();
    float d0 = v0 - mean, d1 = v1 - mean, d2 = v2 - mean;
    red[t] = d0 * d0 + d1 * d1 + d2 * d2;
    __syncthreads();
    for (int o = 128; o; o >>= 1) { if (t < o) red[t] += red[t + o]; __syncthreads(); }
    float var = red[0] * (1.0f / DIM);
    float rstd = rsqrtf(var + 1e-5f);
    float* outr = out + (size_t)row * DIM;
    outr[t]       = d0 * rstd * s[t]       + bp[t];
    outr[t + 256] = d1 * rstd * s[t + 256] + bp[t + 256];
    outr[t + 512] = d2 * rstd * s[t + 512] + bp[t + 512];
}

// ============================================================================
// GEMM: C(MxN) = epi(A(MxK, rowmajor) @ B(KxN, rowmajor) + bias[, resid])
// 128x128 tile, BK=8, 256 threads, 8x8 per thread.
// EPI: 0 = +bias ; 1 = resid + acc + bias ; 2 = gelu(acc + bias)
// ============================================================================
__device__ __forceinline__ float gelu_f(float x) {
    float x3 = x * x * x;
    return 0.5f * x * (1.0f + tanhf(0.7978845608028654f * (x + 0.044715f * x3)));
}

template <int EPI>
__global__ __launch_bounds__(256) void gemm_kernel(
    const float* __restrict__ A, const float* __restrict__ B,
    const float* __restrict__ bias, const float* __restrict__ resid,
    float* __restrict__ C, int M, int N, int K)
{
    __shared__ float As[8][128];
    __shared__ float Bs[8][128];
    int tid = threadIdx.x;
    int rowBase = blockIdx.y * 128;
    int colBase = blockIdx.x * 128;

    int am = tid >> 1;            // 0..127
    int ak = (tid & 1) * 4;       // 0 or 4
    int bk = tid >> 5;            // 0..7
    int bn = (tid & 31) * 4;      // 0..124
    int tm = (tid >> 4) * 8;
    int tn = (tid & 15) * 8;

    const float* Aptr = A + (size_t)(rowBase + am) * K + ak;
    const float* Bptr = B + (size_t)bk * N + colBase + bn;

    float acc[8][8];
    #pragma unroll
    for (int i = 0; i < 8; i++)
        #pragma unroll
        for (int j = 0; j < 8; j++) acc[i][j] = 0.0f;

    for (int k0 = 0; k0 < K; k0 += 8) {
        float4 a4 = *(const float4*)(Aptr + k0);
        float4 b4 = *(const float4*)(Bptr + (size_t)k0 * N);
        As[ak + 0][am] = a4.x; As[ak + 1][am] = a4.y;
        As[ak + 2][am] = a4.z; As[ak + 3][am] = a4.w;
        *(float4*)&Bs[bk][bn] = b4;
        __syncthreads();
        #pragma unroll
        for (int k = 0; k < 8; k++) {
            float4 a0 = *(float4*)&As[k][tm];
            float4 a1 = *(float4*)&As[k][tm + 4];
            float4 b0 = *(float4*)&Bs[k][tn];
            float4 b1 = *(float4*)&Bs[k][tn + 4];
            float ar[8] = {a0.x, a0.y, a0.z, a0.w, a1.x, a1.y, a1.z, a1.w};
            float br[8] = {b0.x, b0.y, b0.z, b0.w, b1.x, b1.y, b1.z, b1.w};
            #pragma unroll
            for (int i = 0; i < 8; i++)
                #pragma unroll
                for (int j = 0; j < 8; j++)
                    acc[i][j] += ar[i] * br[j];
        }
        __syncthreads();
    }

    float bv[8];
    #pragma unroll
    for (int j = 0; j < 8; j++) bv[j] = bias[colBase + tn + j];

    #pragma unroll
    for (int i = 0; i < 8; i++) {
        size_t off = (size_t)(rowBase + tm + i) * N + colBase + tn;
        float o[8];
        #pragma unroll
        for (int j = 0; j < 8; j++) {
            float val = acc[i][j] + bv[j];
            if (EPI == 1) val += resid[off + j];
            if (EPI == 2) val = gelu_f(val);
            o[j] = val;
        }
        *(float4*)(C + off)     = make_float4(o[0], o[1], o[2], o[3]);
        *(float4*)(C + off + 4) = make_float4(o[4], o[5], o[6], o[7]);
    }
}

// ============================================================================
// Attention: one block per (b, head); 8 warps, one query row per warp.
// qkv row layout per token: [q(768) | k(768) | v(768)], head-major h*64+d.
// K/V footprint per block = 100KB -> lives in L1 after first pass.
// ============================================================================
__global__ __launch_bounds__(256) void attn_kernel(const float* __restrict__ qkv,
                                                   float* __restrict__ out) {
    int bh = blockIdx.x;
    int b = bh / HEADS, h = bh % HEADS;
    const float* Qb = qkv + (size_t)b * NTOK * QKVDIM + h * DH;
    const float* Kb = Qb + DIM;
    const float* Vb = Qb + 2 * DIM;
    __shared__ float qs[8][DH];
    __shared__ float ps[8][200];
    int w = threadIdx.x >> 5, lane = threadIdx.x & 31;

    for (int q = w; q < NTOK; q += 8) {
        for (int d = lane; d < DH; d += 32)
            qs[w][d] = Qb[(size_t)q * QKVDIM + d];
        __syncwarp();

        float sc[7];
        float mx = -1e30f;
        #pragma unroll
        for (int i = 0; i < 7; i++) {
            int k = lane + i * 32;
            float s = -1e30f;
            if (k < NTOK) {
                const float* kr = Kb + (size_t)k * QKVDIM;
                float acc = 0.0f;
                #pragma unroll
                for (int d = 0; d < DH; d++) acc += qs[w][d] * kr[d];
                s = acc * 0.125f;
            }
            sc[i] = s;
            mx = fmaxf(mx, s);
        }
        #pragma unroll
        for (int o = 16; o; o >>= 1) mx = fmaxf(mx, __shfl_xor_sync(0xffffffffu, mx, o));

        float sum = 0.0f;
        #pragma unroll
        for (int i = 0; i < 7; i++) {
            int k = lane + i * 32;
            float e = (k < NTOK) ? __expf(sc[i] - mx) : 0.0f;
            sc[i] = e;
            sum += e;
        }
        #pragma unroll
        for (int o = 16; o; o >>= 1) sum += __shfl_xor_sync(0xffffffffu, sum, o);
        float inv = 1.0f / sum;

        #pragma unroll
        for (int i = 0; i < 7; i++) {
            int k = lane + i * 32;
            if (k < NTOK) ps[w][k] = sc[i] * inv;
        }
        __syncwarp();

        #pragma unroll
        for (int r = 0; r < 2; r++) {
            int d = lane + r * 32;
            float acc = 0.0f;
            for (int k = 0; k < NTOK; k++)
                acc += ps[w][k] * Vb[(size_t)k * QKVDIM + d];
            out[((size_t)b * NTOK + q) * DIM + h * DH + d] = acc;
        }
        __syncwarp();
    }
}

// ============================================================================
// Loss: sum |pred - patches| over masked tokens (double accumulators,
// fixed-order two-stage reduction -> deterministic)
// ============================================================================
__global__ void loss_partial_kernel() {
    double acc = 0.0;
    for (size_t i = (size_t)blockIdx.x * blockDim.x + threadIdx.x;
         i < TOTELEM; i += (size_t)gridDim.x * blockDim.x) {
        int bn = (int)(i / DIM);
        if (g_mask[bn]) acc += fabs((double)g_pred[i] - (double)g_patches[i]);
    }
    __shared__ double red[256];
    red[threadIdx.x] = acc;
    __syncthreads();
    for (int o = 128; o; o >>= 1) {
        if (threadIdx.x < o) red[threadIdx.x] += red[threadIdx.x + o];
        __syncthreads();
    }
    if (threadIdx.x == 0) g_part[blockIdx.x] = red[0];
}

__global__ void loss_final_kernel(float* out) {
    __shared__ double red[256];
    int t = threadIdx.x;
    double a = 0.0;
    for (int i = t; i < 1024; i += 256) a += g_part[i];
    red[t] = a;
    __syncthreads();
    for (int o = 128; o; o >>= 1) { if (t < o) red[t] += red[t + o]; __syncthreads(); }
    // mean over (64,98,768) then / 98
    if (t == 0) out[0] = (float)(red[0] / (4816896.0 * 98.0));
}

// ============================================================================
// Launch
// ============================================================================
extern "C" void kernel_launch(void* const* d_in, const int* in_sizes, int n_in,
                              void* d_out, int out_size) {
    const float* img        = (const float*)d_in[0];
    const float* mask_noise = (const float*)d_in[1];
    const float* patch_w    = (const float*)d_in[2];
    const float* patch_b    = (const float*)d_in[3];
    const float* pos_emb    = (const float*)d_in[4];
    const float* mask_token = (const float*)d_in[5];
    const float* ln1_s      = (const float*)d_in[6];
    const float* ln1_b      = (const float*)d_in[7];
    const float* wqkv       = (const float*)d_in[8];
    const float* bqkv       = (const float*)d_in[9];
    const float* wo         = (const float*)d_in[10];
    const float* bo         = (const float*)d_in[11];
    const float* ln2_s      = (const float*)d_in[12];
    const float* ln2_b      = (const float*)d_in[13];
    const float* w1         = (const float*)d_in[14];
    const float* b1         = (const float*)d_in[15];
    const float* w2         = (const float*)d_in[16];
    const float* b2         = (const float*)d_in[17];
    const float* pix_w      = (const float*)d_in[18];
    const float* pix_b      = (const float*)d_in[19];
    float* out = (float*)d_out;

    float *patches, *x, *h, *qkv, *attn, *hid, *pred;
    cudaGetSymbolAddress((void**)&patches, g_patches);
    cudaGetSymbolAddress((void**)&x,       g_x);
    cudaGetSymbolAddress((void**)&h,       g_h);
    cudaGetSymbolAddress((void**)&qkv,     g_qkv);
    cudaGetSymbolAddress((void**)&attn,    g_attn);
    cudaGetSymbolAddress((void**)&hid,     g_hid);
    cudaGetSymbolAddress((void**)&pred,    g_pred);

    int eltBlocks = (int)((TOTELEM + 255) / 256);

    patchify_kernel<<<eltBlocks, 256>>>(img);
    topk_kernel<<<BATCH, 256>>>(mask_noise);

    // embed: x = patches @ patch_w + patch_b
    gemm_kernel<0><<<dim3(DIM / 128, TOKENS / 128), 256>>>(
        patches, patch_w, patch_b, nullptr, x, TOKENS, DIM, DIM);
    finalize_tokens<<<eltBlocks, 256>>>(pos_emb, mask_token);

    for (int l = 0; l < DEPTH; l++) {
        ln_kernel<<<TOKENS, 256>>>(x, ln1_s + l * DIM, ln1_b + l * DIM, h);
        gemm_kernel<0><<<dim3(QKVDIM / 128, TOKENS / 128), 256>>>(
            h, wqkv + (size_t)l * DIM * QKVDIM, bqkv + l * QKVDIM, nullptr,
            qkv, TOKENS, QKVDIM, DIM);
        attn_kernel<<<BATCH * HEADS, 256>>>(qkv, attn);
        gemm_kernel<1><<<dim3(DIM / 128, TOKENS / 128), 256>>>(
            attn, wo + (size_t)l * DIM * DIM, bo + l * DIM, x,
            x, TOKENS, DIM, DIM);
        ln_kernel<<<TOKENS, 256>>>(x, ln2_s + l * DIM, ln2_b + l * DIM, h);
        gemm_kernel<2><<<dim3(MLPDIM / 128, TOKENS / 128), 256>>>(
            h, w1 + (size_t)l * DIM * MLPDIM, b1 + l * MLPDIM, nullptr,
            hid, TOKENS, MLPDIM, DIM);
        gemm_kernel<1><<<dim3(DIM / 128, TOKENS / 128), 256>>>(
            hid, w2 + (size_t)l * MLPDIM * DIM, b2 + l * DIM, x,
            x, TOKENS, DIM, MLPDIM);
    }

    // pixel head over all tokens (loss only reads masked rows)
    gemm_kernel<0><<<dim3(DIM / 128, TOKENS / 128), 256>>>(
        x, pix_w, pix_b, nullptr, pred, TOKENS, DIM, DIM);

    loss_partial_kernel<<<1024, 256>>>();
    loss_final_kernel<<<1, 256>>>(out);
}